// round 1
// baseline (speedup 1.0000x reference)
#include <cuda_runtime.h>
#include <cuda_bf16.h>
#include <math.h>

// Problem constants
#define B_    32
#define H_    32
#define D_    128
#define HID_  4096
#define TH_   12288      // 3*HID
#define BS_   64
#define NBLK_ 16
#define MAXKV_ 1024

// Scratch (no allocations allowed)
__device__ float g_qkv[B_ * TH_];    // [b][j], j<4096 q, 4096..8191 k, 8192.. v (post-RoPE for q,k)
__device__ float g_attn[B_ * HID_];  // [b][h*128+d]

// ---------------------------------------------------------------------------
// Kernel 1: qkv = hidden @ W_pack   (32x4096 @ 4096x12288)
// grid 384, block 128: each block 32 columns; thread = (col, batch-group of 8)
// ---------------------------------------------------------------------------
#define KCHUNK 256
__global__ __launch_bounds__(128) void qkv_kernel(const float* __restrict__ hidden,
                                                  const float* __restrict__ W) {
    __shared__ float sh[32][KCHUNK];     // 32 KB
    const int j  = blockIdx.x * 32 + (threadIdx.x & 31);
    const int bg = (threadIdx.x >> 5) * 8;   // batch group start

    float acc[8];
#pragma unroll
    for (int i = 0; i < 8; i++) acc[i] = 0.f;

    for (int kc = 0; kc < HID_; kc += KCHUNK) {
        __syncthreads();
        // load hidden[0:32][kc:kc+KCHUNK]
        for (int idx = threadIdx.x; idx < 32 * (KCHUNK / 4); idx += 128) {
            int b  = idx / (KCHUNK / 4);
            int kk = (idx % (KCHUNK / 4)) * 4;
            *(float4*)&sh[b][kk] = *(const float4*)&hidden[b * HID_ + kc + kk];
        }
        __syncthreads();

        const float* wp = &W[(size_t)kc * TH_ + j];
#pragma unroll 4
        for (int k = 0; k < KCHUNK; k++) {
            float w = wp[(size_t)k * TH_];
#pragma unroll
            for (int bb = 0; bb < 8; bb++)
                acc[bb] = fmaf(sh[bg + bb][k], w, acc[bb]);
        }
    }
#pragma unroll
    for (int bb = 0; bb < 8; bb++)
        g_qkv[(bg + bb) * TH_ + j] = acc[bb];
}

// ---------------------------------------------------------------------------
// Kernel 2: RoPE on q and k (in place in g_qkv). grid 32 (=B), block 128 (=D)
// ---------------------------------------------------------------------------
__global__ __launch_bounds__(128) void rope_kernel(const int* __restrict__ hist) {
    const int b = blockIdx.x;
    const int d = threadIdx.x;
    const int pos = hist[b];
    const int i = d & 63;

    // double-precision angle with range reduction (robust vs fast-math cosf)
    double invd = exp(-(double)i / 64.0 * 9.210340371976184);  // ln(10000)
    double angd = fmod((double)pos * invd, 6.283185307179586476925286766559);
    float c = cosf((float)angd);
    float s = sinf((float)angd);

    for (int part = 0; part < 2; part++) {          // 0=q, 1=k
        for (int h = 0; h < H_; h++) {
            float* p = &g_qkv[b * TH_ + part * HID_ + h * D_];
            float x  = p[d];
            float xr = (d < 64) ? -p[d + 64] : p[d - 64];
            __syncthreads();                         // all reads before writes
            p[d] = x * c + xr * s;
            __syncthreads();
        }
    }
}

// ---------------------------------------------------------------------------
// Kernel 3: attention. grid = B*H blocks; 256 threads = 8 warps over positions.
// Position s == hist uses the freshly computed (RoPE'd) k and raw v from g_qkv
// (reference writes them into the cache before reading).
// ---------------------------------------------------------------------------
__global__ __launch_bounds__(256) void attn_kernel(const float* __restrict__ kcache,
                                                   const float* __restrict__ vcache,
                                                   const int* __restrict__ hist,
                                                   const int* __restrict__ boff) {
    const int b = blockIdx.x >> 5;
    const int h = blockIdx.x & 31;
    const int lane = threadIdx.x & 31;
    const int wid  = threadIdx.x >> 5;

    __shared__ int   s_blk[NBLK_];
    __shared__ float s_m[8], s_l[8];
    __shared__ float s_acc[8][128];

    if (threadIdx.x < NBLK_) s_blk[threadIdx.x] = boff[b * NBLK_ + threadIdx.x];
    __syncthreads();

    const int pos = hist[b];

    const float4 q4 = *(const float4*)&g_qkv[b * TH_ + h * D_ + lane * 4];

    float  m = -1e30f, l = 0.f;
    float4 acc = make_float4(0.f, 0.f, 0.f, 0.f);

    for (int s = wid; s <= pos; s += 8) {
        const float *kp, *vp;
        if (s == pos) {
            kp = &g_qkv[b * TH_ + HID_     + h * D_];
            vp = &g_qkv[b * TH_ + 2 * HID_ + h * D_];
        } else {
            int base = ((s_blk[s >> 6] * BS_ + (s & 63)) * H_ + h) * D_;
            kp = kcache + base;
            vp = vcache + base;
        }
        float4 k4 = *(const float4*)&kp[lane * 4];
        float4 v4 = *(const float4*)&vp[lane * 4];

        float dt = q4.x * k4.x + q4.y * k4.y + q4.z * k4.z + q4.w * k4.w;
#pragma unroll
        for (int o = 16; o > 0; o >>= 1) dt += __shfl_xor_sync(0xffffffffu, dt, o);
        float sc = dt * 0.08838834764831845f;   // 1/sqrt(128)

        float mn = fmaxf(m, sc);
        float r  = __expf(m - mn);
        float p  = __expf(sc - mn);
        l = l * r + p;
        acc.x = acc.x * r + p * v4.x;
        acc.y = acc.y * r + p * v4.y;
        acc.z = acc.z * r + p * v4.z;
        acc.w = acc.w * r + p * v4.w;
        m = mn;
    }

    if (lane == 0) { s_m[wid] = m; s_l[wid] = l; }
    *(float4*)&s_acc[wid][lane * 4] = acc;
    __syncthreads();

    if (threadIdx.x < 128) {
        const int d = threadIdx.x;
        float M = -1e30f;
#pragma unroll
        for (int w = 0; w < 8; w++) M = fmaxf(M, s_m[w]);
        float L = 0.f, val = 0.f;
#pragma unroll
        for (int w = 0; w < 8; w++) {
            float r = __expf(s_m[w] - M);
            L   += s_l[w] * r;
            val += s_acc[w][d] * r;
        }
        g_attn[b * HID_ + h * D_ + d] = val / L;
    }
}

// ---------------------------------------------------------------------------
// Kernel 4: out = attn @ Wo^T. grid 256, block 256 = 8 warps, warp -> 2 rows i.
// attn tiles staged in smem so the loop stays FMA-bound.
// ---------------------------------------------------------------------------
__global__ __launch_bounds__(256) void oproj_kernel(const float* __restrict__ Wo,
                                                    float* __restrict__ out) {
    __shared__ float s_attn[32][256];    // 32 KB
    const int lane = threadIdx.x & 31;
    const int wid  = threadIdx.x >> 5;
    const int i0   = blockIdx.x * 16 + wid * 2;

    float acc0[32], acc1[32];
#pragma unroll
    for (int b = 0; b < 32; b++) { acc0[b] = 0.f; acc1[b] = 0.f; }

    for (int jt = 0; jt < HID_; jt += 256) {
        __syncthreads();
        for (int idx = threadIdx.x; idx < 32 * 64; idx += 256) {
            int b  = idx >> 6;
            int jj = (idx & 63) << 2;
            *(float4*)&s_attn[b][jj] = *(const float4*)&g_attn[b * HID_ + jt + jj];
        }
        __syncthreads();

        const float* w0 = &Wo[(size_t)i0 * HID_ + jt];
        const float* w1 = w0 + HID_;
#pragma unroll
        for (int part = 0; part < 2; part++) {
            int j0 = part * 128 + lane * 4;
            float4 wa = *(const float4*)&w0[j0];
            float4 wb = *(const float4*)&w1[j0];
#pragma unroll
            for (int b = 0; b < 32; b++) {
                float4 a = *(const float4*)&s_attn[b][j0];
                acc0[b] += a.x * wa.x + a.y * wa.y + a.z * wa.z + a.w * wa.w;
                acc1[b] += a.x * wb.x + a.y * wb.y + a.z * wb.z + a.w * wb.w;
            }
        }
    }

    float r0 = 0.f, r1 = 0.f;
#pragma unroll
    for (int b = 0; b < 32; b++) {
        float v0 = acc0[b], v1 = acc1[b];
#pragma unroll
        for (int o = 16; o > 0; o >>= 1) {
            v0 += __shfl_xor_sync(0xffffffffu, v0, o);
            v1 += __shfl_xor_sync(0xffffffffu, v1, o);
        }
        if (lane == b) { r0 = v0; r1 = v1; }
    }
    out[lane * HID_ + i0]     = r0;
    out[lane * HID_ + i0 + 1] = r1;
}

// ---------------------------------------------------------------------------
extern "C" void kernel_launch(void* const* d_in, const int* in_sizes, int n_in,
                              void* d_out, int out_size) {
    const float* hidden = (const float*)d_in[0];
    const float* W      = (const float*)d_in[1];
    const float* Wo     = (const float*)d_in[2];
    const float* kcache = (const float*)d_in[3];
    const float* vcache = (const float*)d_in[4];
    const int*   hist   = (const int*)d_in[5];
    const int*   boff   = (const int*)d_in[6];
    float*       out    = (float*)d_out;

    qkv_kernel<<<TH_ / 32, 128>>>(hidden, W);
    rope_kernel<<<B_, 128>>>(hist);
    attn_kernel<<<B_ * H_, 256>>>(kcache, vcache, hist, boff);
    oproj_kernel<<<HID_ / 16, 256>>>(Wo, out);
}

// round 2
// speedup vs baseline: 1.1954x; 1.1954x over previous
#include <cuda_runtime.h>
#include <cuda_bf16.h>
#include <math.h>

#define B_    32
#define H_    32
#define D_    128
#define HID_  4096
#define TH_   12288      // 3*HID
#define BS_   64
#define NBLK_ 16

__device__ float g_qkv[B_ * TH_];    // [b][j] ; j<4096 q, 4096..8191 k, 8192.. v
__device__ float g_attn[B_ * HID_];  // [b][h*128+d]

typedef unsigned long long u64;

// ---- packed f32x2 helpers (sm_103a dual-FP32 path) ----
__device__ __forceinline__ u64 pack2(float lo, float hi) {
    u64 r; asm("mov.b64 %0, {%1, %2};" : "=l"(r) : "f"(lo), "f"(hi)); return r;
}
__device__ __forceinline__ u64 fma2(u64 a, u64 b, u64 c) {
    u64 d; asm("fma.rn.f32x2 %0, %1, %2, %3;" : "=l"(d) : "l"(a), "l"(b), "l"(c)); return d;
}
__device__ __forceinline__ float hadd2(u64 a) {
    float lo, hi; asm("mov.b64 {%0, %1}, %2;" : "=f"(lo), "=f"(hi) : "l"(a)); return lo + hi;
}

// ---------------------------------------------------------------------------
// Kernel 1: qkv = hidden @ W_pack   (32x4096 @ 4096x12288), f32x2-packed over k
// grid 384, block 128: 32 columns/block; thread = (col lane, batch-group of 8)
// ---------------------------------------------------------------------------
#define KCHUNK 256
__global__ __launch_bounds__(128) void qkv_kernel(const float* __restrict__ hidden,
                                                  const float* __restrict__ W) {
    __shared__ float sh[32][KCHUNK];     // 32 KB
    const int j  = blockIdx.x * 32 + (threadIdx.x & 31);
    const int bg = (threadIdx.x >> 5) * 8;

    u64 accA[8], accB[8];
#pragma unroll
    for (int i = 0; i < 8; i++) { accA[i] = 0ull; accB[i] = 0ull; }

    const float* wbase = W + j;
    for (int kc = 0; kc < HID_; kc += KCHUNK) {
        __syncthreads();
        for (int idx = threadIdx.x; idx < 32 * (KCHUNK / 4); idx += 128) {
            int b  = idx / (KCHUNK / 4);
            int kk = (idx % (KCHUNK / 4)) * 4;
            *(float4*)&sh[b][kk] = *(const float4*)&hidden[b * HID_ + kc + kk];
        }
        __syncthreads();

        const float* wp = wbase + (size_t)kc * TH_;
#pragma unroll 2
        for (int k = 0; k < KCHUNK; k += 4) {
            float w0 = wp[0];
            float w1 = wp[TH_];
            float w2 = wp[2 * TH_];
            float w3 = wp[3 * TH_];
            wp += 4 * (size_t)TH_;
            u64 w01 = pack2(w0, w1);
            u64 w23 = pack2(w2, w3);
#pragma unroll
            for (int bb = 0; bb < 8; bb++) {
                ulonglong2 s2 = *(const ulonglong2*)&sh[bg + bb][k];   // LDS.128 broadcast
                accA[bb] = fma2(s2.x, w01, accA[bb]);
                accB[bb] = fma2(s2.y, w23, accB[bb]);
            }
        }
    }
#pragma unroll
    for (int bb = 0; bb < 8; bb++)
        g_qkv[(bg + bb) * TH_ + j] = hadd2(accA[bb]) + hadd2(accB[bb]);
}

// ---------------------------------------------------------------------------
// Kernel 2: RoPE on q and k (in place in g_qkv). grid 32 (=B), block 128 (=D)
// ---------------------------------------------------------------------------
__global__ __launch_bounds__(128) void rope_kernel(const int* __restrict__ hist) {
    const int b = blockIdx.x;
    const int d = threadIdx.x;
    const int pos = hist[b];
    const int i = d & 63;

    double invd = exp(-(double)i / 64.0 * 9.210340371976184);  // ln(10000)
    double angd = fmod((double)pos * invd, 6.283185307179586476925286766559);
    float c = cosf((float)angd);
    float s = sinf((float)angd);

    for (int part = 0; part < 2; part++) {
        for (int h = 0; h < H_; h++) {
            float* p = &g_qkv[b * TH_ + part * HID_ + h * D_];
            float x  = p[d];
            float xr = (d < 64) ? -p[d + 64] : p[d - 64];
            __syncthreads();
            p[d] = x * c + xr * s;
            __syncthreads();
        }
    }
}

// ---------------------------------------------------------------------------
// Kernel 3: attention. grid = B*H; 8 warps over positions, 2-way s unroll.
// s == hist handled once outside the hot loop (fresh k/v from g_qkv).
// ---------------------------------------------------------------------------
__global__ __launch_bounds__(256) void attn_kernel(const float* __restrict__ kcache,
                                                   const float* __restrict__ vcache,
                                                   const int* __restrict__ hist,
                                                   const int* __restrict__ boff) {
    const int b = blockIdx.x >> 5;
    const int h = blockIdx.x & 31;
    const int lane = threadIdx.x & 31;
    const int wid  = threadIdx.x >> 5;

    __shared__ int   s_blk[NBLK_];
    __shared__ float s_m[8], s_l[8];
    __shared__ float s_acc[8][128];

    if (threadIdx.x < NBLK_) s_blk[threadIdx.x] = boff[b * NBLK_ + threadIdx.x];
    __syncthreads();

    const int pos = hist[b];
    const float4 q4 = *(const float4*)&g_qkv[b * TH_ + h * D_ + lane * 4];
    const float scale = 0.08838834764831845f;  // 1/sqrt(128)

    float  m = -1e30f, l = 0.f;
    float4 acc = make_float4(0.f, 0.f, 0.f, 0.f);

    int s = wid;
    for (; s + 8 < pos; s += 16) {
        int a0 = ((s_blk[s >> 6] * BS_ + (s & 63)) * H_ + h) * D_;
        int s1 = s + 8;
        int a1 = ((s_blk[s1 >> 6] * BS_ + (s1 & 63)) * H_ + h) * D_;
        float4 k0 = *(const float4*)&kcache[a0 + lane * 4];
        float4 v0 = *(const float4*)&vcache[a0 + lane * 4];
        float4 k1 = *(const float4*)&kcache[a1 + lane * 4];
        float4 v1 = *(const float4*)&vcache[a1 + lane * 4];

        float d0 = q4.x * k0.x + q4.y * k0.y + q4.z * k0.z + q4.w * k0.w;
        float d1 = q4.x * k1.x + q4.y * k1.y + q4.z * k1.z + q4.w * k1.w;
#pragma unroll
        for (int o = 16; o > 0; o >>= 1) {
            d0 += __shfl_xor_sync(0xffffffffu, d0, o);
            d1 += __shfl_xor_sync(0xffffffffu, d1, o);
        }
        float sc0 = d0 * scale, sc1 = d1 * scale;

        float mn = fmaxf(m, sc0);
        float r  = __expf(m - mn);
        float p  = __expf(sc0 - mn);
        l = l * r + p;
        acc.x = acc.x * r + p * v0.x; acc.y = acc.y * r + p * v0.y;
        acc.z = acc.z * r + p * v0.z; acc.w = acc.w * r + p * v0.w;
        m = mn;

        mn = fmaxf(m, sc1);
        r  = __expf(m - mn);
        p  = __expf(sc1 - mn);
        l = l * r + p;
        acc.x = acc.x * r + p * v1.x; acc.y = acc.y * r + p * v1.y;
        acc.z = acc.z * r + p * v1.z; acc.w = acc.w * r + p * v1.w;
        m = mn;
    }
    for (; s < pos; s += 8) {
        int a0 = ((s_blk[s >> 6] * BS_ + (s & 63)) * H_ + h) * D_;
        float4 k0 = *(const float4*)&kcache[a0 + lane * 4];
        float4 v0 = *(const float4*)&vcache[a0 + lane * 4];
        float d0 = q4.x * k0.x + q4.y * k0.y + q4.z * k0.z + q4.w * k0.w;
#pragma unroll
        for (int o = 16; o > 0; o >>= 1) d0 += __shfl_xor_sync(0xffffffffu, d0, o);
        float sc0 = d0 * scale;
        float mn = fmaxf(m, sc0);
        float r  = __expf(m - mn);
        float p  = __expf(sc0 - mn);
        l = l * r + p;
        acc.x = acc.x * r + p * v0.x; acc.y = acc.y * r + p * v0.y;
        acc.z = acc.z * r + p * v0.z; acc.w = acc.w * r + p * v0.w;
        m = mn;
    }
    if ((pos & 7) == wid) {     // fresh k/v at s == pos (reference writes cache first)
        const float* kp = &g_qkv[b * TH_ + HID_     + h * D_];
        const float* vp = &g_qkv[b * TH_ + 2 * HID_ + h * D_];
        float4 k0 = *(const float4*)&kp[lane * 4];
        float4 v0 = *(const float4*)&vp[lane * 4];
        float d0 = q4.x * k0.x + q4.y * k0.y + q4.z * k0.z + q4.w * k0.w;
#pragma unroll
        for (int o = 16; o > 0; o >>= 1) d0 += __shfl_xor_sync(0xffffffffu, d0, o);
        float sc0 = d0 * scale;
        float mn = fmaxf(m, sc0);
        float r  = __expf(m - mn);
        float p  = __expf(sc0 - mn);
        l = l * r + p;
        acc.x = acc.x * r + p * v0.x; acc.y = acc.y * r + p * v0.y;
        acc.z = acc.z * r + p * v0.z; acc.w = acc.w * r + p * v0.w;
        m = mn;
    }

    if (lane == 0) { s_m[wid] = m; s_l[wid] = l; }
    *(float4*)&s_acc[wid][lane * 4] = acc;
    __syncthreads();

    if (threadIdx.x < 128) {
        const int d = threadIdx.x;
        float M = -1e30f;
#pragma unroll
        for (int w = 0; w < 8; w++) M = fmaxf(M, s_m[w]);
        float L = 0.f, val = 0.f;
#pragma unroll
        for (int w = 0; w < 8; w++) {
            float r = __expf(s_m[w] - M);
            L   += s_l[w] * r;
            val += s_acc[w][d] * r;
        }
        g_attn[b * HID_ + h * D_ + d] = val / L;
    }
}

// ---------------------------------------------------------------------------
// Kernel 4: out = attn @ Wo^T. grid 256 (128 i-tiles x 2 b-halves), block 256.
// Warp -> 4 rows of Wo, 16 batches; attn tile reused across 4 rows (halved LDS).
// ---------------------------------------------------------------------------
__global__ __launch_bounds__(256, 2) void oproj_kernel(const float* __restrict__ Wo,
                                                       float* __restrict__ out) {
    __shared__ float s_attn[16][256];    // 16 KB
    const int lane = threadIdx.x & 31;
    const int wid  = threadIdx.x >> 5;
    const int tile = blockIdx.x >> 1;         // 0..127
    const int bh   = (blockIdx.x & 1) * 16;   // batch half
    const int i0   = tile * 32 + wid * 4;

    float acc[4][16];
#pragma unroll
    for (int r = 0; r < 4; r++)
#pragma unroll
        for (int b = 0; b < 16; b++) acc[r][b] = 0.f;

    for (int jt = 0; jt < HID_; jt += 256) {
        __syncthreads();
        for (int idx = threadIdx.x; idx < 16 * 64; idx += 256) {
            int b  = idx >> 6;
            int jj = (idx & 63) << 2;
            *(float4*)&s_attn[b][jj] = *(const float4*)&g_attn[(bh + b) * HID_ + jt + jj];
        }
        __syncthreads();

        const float* w = Wo + (size_t)i0 * HID_ + jt;
#pragma unroll
        for (int part = 0; part < 2; part++) {
            int j0 = part * 128 + lane * 4;
            float4 w0 = *(const float4*)&w[j0];
            float4 w1 = *(const float4*)&w[HID_ + j0];
            float4 w2 = *(const float4*)&w[2 * HID_ + j0];
            float4 w3 = *(const float4*)&w[3 * HID_ + j0];
#pragma unroll
            for (int b = 0; b < 16; b++) {
                float4 a = *(const float4*)&s_attn[b][j0];
                acc[0][b] += a.x * w0.x + a.y * w0.y + a.z * w0.z + a.w * w0.w;
                acc[1][b] += a.x * w1.x + a.y * w1.y + a.z * w1.z + a.w * w1.w;
                acc[2][b] += a.x * w2.x + a.y * w2.y + a.z * w2.z + a.w * w2.w;
                acc[3][b] += a.x * w3.x + a.y * w3.y + a.z * w3.z + a.w * w3.w;
            }
        }
    }

#pragma unroll
    for (int r = 0; r < 4; r++) {
        float res = 0.f;
#pragma unroll
        for (int b = 0; b < 16; b++) {
            float v = acc[r][b];
#pragma unroll
            for (int o = 16; o > 0; o >>= 1) v += __shfl_xor_sync(0xffffffffu, v, o);
            if (lane == b) res = v;
        }
        if (lane < 16) out[(bh + lane) * HID_ + i0 + r] = res;
    }
}

// ---------------------------------------------------------------------------
extern "C" void kernel_launch(void* const* d_in, const int* in_sizes, int n_in,
                              void* d_out, int out_size) {
    const float* hidden = (const float*)d_in[0];
    const float* W      = (const float*)d_in[1];
    const float* Wo     = (const float*)d_in[2];
    const float* kcache = (const float*)d_in[3];
    const float* vcache = (const float*)d_in[4];
    const int*   hist   = (const int*)d_in[5];
    const int*   boff   = (const int*)d_in[6];
    float*       out    = (float*)d_out;

    qkv_kernel<<<TH_ / 32, 128>>>(hidden, W);
    rope_kernel<<<B_, 128>>>(hist);
    attn_kernel<<<B_ * H_, 256>>>(kcache, vcache, hist, boff);
    oproj_kernel<<<256, 256>>>(Wo, out);
}